// round 4
// baseline (speedup 1.0000x reference)
#include <cuda_runtime.h>
#include <cstdint>

#define BATCH   16384
#define NIN     784
#define TSTEPS  100
#define NOUT    10
#define IPAD    12          // padded o-stride for 16B-aligned stores

// ---- scratch (static device globals: allocation-free) ----
__device__ unsigned g_xi[BATCH * NIN];                       // 51.4 MB: ceil(x * 2^23)
__device__ float    g_I[(size_t)TSTEPS * BATCH * IPAD];      // 78.6 MB: I[t][b][o]

// ---------------- threefry2x32 (exact JAX semantics) ----------------
__device__ __forceinline__ unsigned rotl32(unsigned v, int s) {
    return __funnelshift_l(v, v, s);   // 1x SHF
}

struct U2 { unsigned a, b; };

__device__ __forceinline__ U2 threefry2x32(unsigned k0, unsigned k1,
                                           unsigned c0, unsigned c1) {
    unsigned k2 = k0 ^ k1 ^ 0x1BD11BDAu;
    unsigned x0 = c0 + k0;
    unsigned x1 = c1 + k1;
#define TFR(r) { x0 += x1; x1 = rotl32(x1, (r)) ^ x0; }
    TFR(13) TFR(15) TFR(26) TFR(6)
    x0 += k1; x1 += k2 + 1u;
    TFR(17) TFR(29) TFR(16) TFR(24)
    x0 += k2; x1 += k0 + 2u;
    TFR(13) TFR(15) TFR(26) TFR(6)
    x0 += k0; x1 += k1 + 3u;
    TFR(17) TFR(29) TFR(16) TFR(24)
    x0 += k1; x1 += k2 + 4u;
    TFR(13) TFR(15) TFR(26) TFR(6)
    x0 += k2; x1 += k0 + 5u;
#undef TFR
    return {x0, x1};
}

// ---------------- phase 0: x -> integer spike thresholds ----------------
// JAX partitionable random_bits (32-bit): bits = out0 ^ out1 of
// threefry(key_t, (hi=0, lo=flat_index)).  uniform: u = (bits>>9)*2^-23 exactly
// ((1+f)-1 is Sterbenz-exact; *(1-0)+0 and max(0,.) are identities).
// spike  <=>  u < x  <=>  (bits>>9) < ceil(x * 2^23).
// x*2^23 is an exact exponent shift; __float2uint_ru is an exact ceil, so this
// integer compare is bit-identical to the reference float compare.
__global__ __launch_bounds__(256) void snn_prep(const float* __restrict__ x) {
    int i = blockIdx.x * 256 + threadIdx.x;
    if (i < BATCH * NIN)
        g_xi[i] = __float2uint_ru(x[i] * 8388608.0f);
}

// ---------------- phase 1: per-(b,t) Poisson encode + spike matvec ----------------
__global__ __launch_bounds__(256) void snn_phase1(const float* __restrict__ W) {
    // W packed as f32x2 o-pairs: s_w2[i*6 + k] = {W[2k][i], W[2k+1][i]}
    // row padded to 6 (48B). 37,632 B static shared.
    __shared__ unsigned long long s_w2[NIN * 6];
    for (int idx = threadIdx.x; idx < NIN * 5; idx += 256) {
        int i = idx / 5, k = idx - 5 * (idx / 5);
        float lo = W[(2 * k)     * NIN + i];
        float hi = W[(2 * k + 1) * NIN + i];
        unsigned long long p;
        asm("mov.b64 %0, {%1, %2};" : "=l"(p) : "f"(lo), "f"(hi));
        s_w2[i * 6 + k] = p;
    }
    __syncthreads();

    int item = blockIdx.x * 256 + threadIdx.x;   // exactly BATCH*TSTEPS items
    int b = item / TSTEPS;
    int t = item - b * TSTEPS;                   // warp spans <=2 b values

    // foldlike split: key_t = full output pair of threefry((0,42), (0,t))
    U2 kt = threefry2x32(0u, 42u, 0u, (unsigned)t);
    const unsigned k0 = kt.a, k1 = kt.b;

    unsigned long long acc[5];
#pragma unroll
    for (int k = 0; k < 5; k++) acc[k] = 0ull;

    const unsigned* __restrict__ xip = g_xi + b * NIN;   // lanes share b -> L1 broadcast
    const unsigned idx0 = (unsigned)(b * NIN);           // flat iota base, < 2^24

    for (int i0 = 0; i0 < NIN; i0 += 4) {
        uint4 xi4 = *(const uint4*)(xip + i0);
#pragma unroll
        for (int u = 0; u < 4; u++) {
            unsigned xi = (u == 0) ? xi4.x : (u == 1) ? xi4.y : (u == 2) ? xi4.z : xi4.w;
            // partitionable 32-bit random_bits: out0 ^ out1, counter (0, j)
            U2 r = threefry2x32(k0, k1, 0u, idx0 + (unsigned)(i0 + u));
            unsigned m = (r.a ^ r.b) >> 9;        // 23 mantissa bits
            const unsigned long long* wr = s_w2 + (i0 + u) * 6;
            // spike => acc[k] += w[k] (packed f32x2, predicated: no select/pack;
            // acc bit-identical on no-spike; acc+w rounds identically to fma(1,w,acc))
            asm("{\n\t"
                ".reg .pred p;\n\t"
                "setp.lt.u32 p, %5, %6;\n\t"
                "@p add.rn.f32x2 %0, %0, %7;\n\t"
                "@p add.rn.f32x2 %1, %1, %8;\n\t"
                "@p add.rn.f32x2 %2, %2, %9;\n\t"
                "@p add.rn.f32x2 %3, %3, %10;\n\t"
                "@p add.rn.f32x2 %4, %4, %11;\n\t"
                "}"
                : "+l"(acc[0]), "+l"(acc[1]), "+l"(acc[2]),
                  "+l"(acc[3]), "+l"(acc[4])
                : "r"(m), "r"(xi),
                  "l"(wr[0]), "l"(wr[1]), "l"(wr[2]), "l"(wr[3]), "l"(wr[4]));
        }
    }

    // I[t][b][0..9], padded stride 12 -> base byte offset multiple of 48
    unsigned long long* dst =
        (unsigned long long*)(g_I + ((size_t)t * BATCH + b) * IPAD);
#pragma unroll
    for (int k = 0; k < 5; k++) dst[k] = acc[k];
}

// ---------------- phase 2: LIF scan over t, per (b,o) ----------------
__global__ __launch_bounds__(256) void snn_phase2(float* __restrict__ out) {
    int id = blockIdx.x * 256 + threadIdx.x;
    if (id >= BATCH * NOUT) return;
    int b = id / NOUT, o = id - b * NOUT;
    const float* __restrict__ src = g_I + (size_t)b * IPAD + o;

    float v = 0.0f, acc = 0.0f;
#pragma unroll 4
    for (int t = 0; t < TSTEPS; t++) {
        float I = src[(size_t)t * BATCH * IPAD];
        v = v + (I - v) * 0.5f;          // /2.0 == *0.5 exactly
        if (v >= 1.0f) { acc += 1.0f; v = 0.0f; }   // sign-exact vs (v-1>=0)
    }
    out[id] = __fdiv_rn(acc, 100.0f);    // IEEE div regardless of fast-math flags
}

// ---------------- launch ----------------
extern "C" void kernel_launch(void* const* d_in, const int* in_sizes, int n_in,
                              void* d_out, int out_size) {
    // Select inputs by size, not position: x has 16384*784 = 12,845,056 elems,
    // W has 10*784 = 7,840.
    const float* x = (const float*)d_in[0];
    const float* W = (const float*)d_in[1];
    if (n_in >= 2 && in_sizes[0] == NOUT * NIN) {   // order reversed
        W = (const float*)d_in[0];
        x = (const float*)d_in[1];
    }
    float* out = (float*)d_out;               // [16384,10]

    snn_prep  <<<(BATCH * NIN + 255) / 256, 256>>>(x);
    snn_phase1<<<(BATCH * TSTEPS) / 256,    256>>>(W);
    snn_phase2<<<(BATCH * NOUT + 255) / 256, 256>>>(out);
}